// round 6
// baseline (speedup 1.0000x reference)
#include <cuda_runtime.h>
#include <math.h>

#define CCH 62
#define TT  2000
#define NB  256
#define TIL 128
#define NCHUNK 4
#define TILES_PER_CHUNK 4   // 16 tiles total / 4 chunks

// deterministic per-chunk partial sums (no atomics)
__device__ float g_part[NB * NCHUNK * 64 * 64];   // partial sum x x^T
__device__ float g_sxp [NB * NCHUNK * 64];        // partial sum x

// ---------------------------------------------------------------------------
// Kernel 1: partial covariance sums. grid = 4*B; CTA (b, chunk) handles 4
// tiles of 128 samples. Full 16x16 block grid (all 256 threads active).
// ---------------------------------------------------------------------------
__global__ __launch_bounds__(256, 2) void cov_kernel(const float* __restrict__ x)
{
    __shared__ __align__(16) float xs[64 * 132];
    __shared__ float ssum[64];

    const int blk   = blockIdx.x;
    const int b     = blk >> 2;
    const int chunk = blk & 3;
    const int tid   = threadIdx.x;
    const int ti    = tid >> 4;
    const int tj    = tid & 15;

    float acc[16];
#pragma unroll
    for (int r = 0; r < 16; r++) acc[r] = 0.f;
    float mysum = 0.f;

    const float* xb = x + (size_t)b * CCH * TT;

    for (int tt = 0; tt < TILES_PER_CHUNK; tt++) {
        const int t0 = (chunk * TILES_PER_CHUNK + tt) * TIL;
        for (int idx = tid; idx < 64 * TIL; idx += 256) {
            const int c  = idx >> 7;
            const int tl = idx & 127;
            const int t  = t0 + tl;
            float v = 0.f;
            if (c < CCH && t < TT) v = xb[c * TT + t];
            xs[c * 132 + tl] = v;
        }
        __syncthreads();

        if (tid < CCH) {
            const float4* rp = (const float4*)(xs + tid * 132);
#pragma unroll 8
            for (int tl = 0; tl < 32; tl++) {
                const float4 v = rp[tl];
                mysum += (v.x + v.y) + (v.z + v.w);
            }
        }

        {
            const float4* r0 = (const float4*)(xs + (4 * ti + 0) * 132);
            const float4* r1 = (const float4*)(xs + (4 * ti + 1) * 132);
            const float4* r2 = (const float4*)(xs + (4 * ti + 2) * 132);
            const float4* r3 = (const float4*)(xs + (4 * ti + 3) * 132);
            const float4* c0 = (const float4*)(xs + (4 * tj + 0) * 132);
            const float4* c1 = (const float4*)(xs + (4 * tj + 1) * 132);
            const float4* c2 = (const float4*)(xs + (4 * tj + 2) * 132);
            const float4* c3 = (const float4*)(xs + (4 * tj + 3) * 132);

#pragma unroll 2
            for (int tl = 0; tl < 32; tl++) {
                const float4 a0 = r0[tl], a1 = r1[tl], a2 = r2[tl], a3 = r3[tl];
                const float4 b0 = c0[tl], b1 = c1[tl], b2 = c2[tl], b3 = c3[tl];
#define DOT4(A, B) ((A.x * B.x + A.y * B.y) + (A.z * B.z + A.w * B.w))
                acc[0]  += DOT4(a0, b0); acc[1]  += DOT4(a0, b1);
                acc[2]  += DOT4(a0, b2); acc[3]  += DOT4(a0, b3);
                acc[4]  += DOT4(a1, b0); acc[5]  += DOT4(a1, b1);
                acc[6]  += DOT4(a1, b2); acc[7]  += DOT4(a1, b3);
                acc[8]  += DOT4(a2, b0); acc[9]  += DOT4(a2, b1);
                acc[10] += DOT4(a2, b2); acc[11] += DOT4(a2, b3);
                acc[12] += DOT4(a3, b0); acc[13] += DOT4(a3, b1);
                acc[14] += DOT4(a3, b2); acc[15] += DOT4(a3, b3);
#undef DOT4
            }
        }
        __syncthreads();
    }

    if (tid < 64) ssum[tid] = (tid < CCH) ? mysum : 0.f;
    __syncthreads();

    float* outp = g_part + (size_t)blk * 4096;
#pragma unroll
    for (int r = 0; r < 4; r++) {
#pragma unroll
        for (int u = 0; u < 4; u++)
            outp[(4 * ti + r) * 64 + 4 * tj + u] = acc[r * 4 + u];
    }
    if (tid < 64) g_sxp[blk * 64 + tid] = ssum[tid];
}

// ---------------------------------------------------------------------------
// Kernel 2: assemble cov, A = W Cov W^T + eps I -> fused two-sided Jacobi ->
//           log-map GEMM -> triu vec -> proj+relu -> head. One CTA per batch.
// ---------------------------------------------------------------------------
__global__ __launch_bounds__(256, 2) void eig_kernel(
    const float* __restrict__ conv_w,
    const float* __restrict__ proj_w, const float* __restrict__ proj_b,
    const float* __restrict__ head_w, const float* __restrict__ head_b,
    float* __restrict__ out)
{
    __shared__ float Asm[64 * 65];                  // stride 65
    __shared__ __align__(16) float Vsm[64 * 64];    // stride 64 (float2/4 rows)
    __shared__ float Wbuf[62 * 62];                 // W in prologue; scratch after
    __shared__ float sxs[64];                       // OWN array: no aliasing with Wbuf!

    float* vec  = Wbuf;              // [1953]   (Wbuf dead when these are live)
    float* logl = Wbuf + 2048;       // [64]
    float* feat = Wbuf + 2112;       // [64]
    float* red  = Wbuf + 2176;       // [9]

    const int b    = blockIdx.x;
    const int tid  = threadIdx.x;
    const int wid  = tid >> 5;
    const int lane = tid & 31;
    const int ti   = tid >> 4;
    const int tj   = tid & 15;

    // ---- channel sums (separate smem; safe alongside W load) ----
    if (tid < 64) {
        float s = 0.f;
#pragma unroll
        for (int c = 0; c < NCHUNK; c++) s += g_sxp[(b * NCHUNK + c) * 64 + tid];
        sxs[tid] = s;
    }
    // ---- W ----
    for (int idx = tid; idx < 62 * 62; idx += 256) Wbuf[idx] = conv_w[idx];
    __syncthreads();

    // ---- assemble cov into Asm with mean correction ----
    for (int idx = tid; idx < 4096; idx += 256) {
        const int i = idx >> 6, j = idx & 63;
        float s = 0.f;
#pragma unroll
        for (int c = 0; c < NCHUNK; c++) s += g_part[(size_t)(b * NCHUNK + c) * 4096 + idx];
        Asm[i * 65 + j] = (s - sxs[i] * sxs[j] * (1.f / 2000.f)) * (1.f / 1999.f);
    }
    __syncthreads();

    // ---- M = W * Cov  -> Vsm ----
    {
        float acc[16];
#pragma unroll
        for (int r = 0; r < 16; r++) acc[r] = 0.f;
        for (int k = 0; k < 62; k++) {
            float wv[4], cv[4];
#pragma unroll
            for (int r = 0; r < 4; r++) {
                const int i = 4 * ti + r;
                wv[r] = (i < 62) ? Wbuf[i * 62 + k] : 0.f;
            }
#pragma unroll
            for (int u = 0; u < 4; u++) cv[u] = Asm[k * 65 + 4 * tj + u];
#pragma unroll
            for (int r = 0; r < 4; r++)
#pragma unroll
                for (int u = 0; u < 4; u++) acc[r * 4 + u] += wv[r] * cv[u];
        }
#pragma unroll
        for (int r = 0; r < 4; r++)
#pragma unroll
            for (int u = 0; u < 4; u++)
                Vsm[(4 * ti + r) * 64 + 4 * tj + u] = acc[r * 4 + u];
    }
    __syncthreads();

    // ---- A = M * W^T  -> Asm ----
    {
        float acc[16];
#pragma unroll
        for (int r = 0; r < 16; r++) acc[r] = 0.f;
        for (int k = 0; k < 62; k++) {
            float mv[4], wv[4];
#pragma unroll
            for (int r = 0; r < 4; r++) mv[r] = Vsm[(4 * ti + r) * 64 + k];
#pragma unroll
            for (int u = 0; u < 4; u++) {
                const int j = 4 * tj + u;
                wv[u] = (j < 62) ? Wbuf[j * 62 + k] : 0.f;
            }
#pragma unroll
            for (int r = 0; r < 4; r++)
#pragma unroll
                for (int u = 0; u < 4; u++) acc[r * 4 + u] += mv[r] * wv[u];
        }
#pragma unroll
        for (int r = 0; r < 4; r++)
#pragma unroll
            for (int u = 0; u < 4; u++)
                Asm[(4 * ti + r) * 65 + 4 * tj + u] = acc[r * 4 + u];
    }
    __syncthreads();

    // ---- symmetrize + SPD eps + pad diag ----
    {
        float v[16];
#pragma unroll
        for (int r = 0; r < 4; r++)
#pragma unroll
            for (int u = 0; u < 4; u++) {
                const int i = 4 * ti + r, j = 4 * tj + u;
                v[r * 4 + u] = 0.5f * (Asm[i * 65 + j] + Asm[j * 65 + i]);
            }
        __syncthreads();
#pragma unroll
        for (int r = 0; r < 4; r++)
#pragma unroll
            for (int u = 0; u < 4; u++) {
                const int i = 4 * ti + r, j = 4 * tj + u;
                float val = v[r * 4 + u];
                if (i == j) val = (i < 62) ? val + 1e-3f : 1.0f;
                Asm[i * 65 + j] = val;
            }
    }
    // V = I
    for (int idx = tid; idx < 4096; idx += 256)
        Vsm[idx] = ((idx >> 6) == (idx & 63)) ? 1.f : 0.f;
    __syncthreads();

    // ---- fused two-sided parallel Jacobi ----
    // Relative rotation-skip: skip pair iff apq^2 <= 1e-12 * app * aqq;
    // bounds the induced log_cov error by ~1e-6 per pair at any eigenvalue
    // scale (threshold shrinks with sqrt(app*aqq) exactly where 1/lambda
    // amplification grows).
    const float tol = 1e-5f;
    for (int sweep = 0; sweep < 9; sweep++) {
        for (int r = 0; r < 63; r++) {
            int p, q;
            if (lane == 0) { p = 63; q = r; }
            else {
                p = r + lane;      if (p >= 63) p -= 63;
                q = r + 63 - lane; if (q >= 63) q -= 63;
            }
            const float app = Asm[p * 65 + p];
            const float aqq = Asm[q * 65 + q];
            const float apq = Asm[p * 65 + q];
            float cO = 1.f, sO = 0.f;
            if (apq * apq > 1e-12f * app * aqq) {
                const float tau = (aqq - app) / (2.f * apq);
                const float t2  = ((tau >= 0.f) ? 1.f : -1.f) /
                                  (fabsf(tau) + sqrtf(1.f + tau * tau));
                cO = rsqrtf(1.f + t2 * t2);
                sO = t2 * cO;
            }
            const int pqPack = p | (q << 8);
            const unsigned rotmask = __ballot_sync(0xffffffffu, sO != 0.f);

            if (rotmask != 0u) {
                __syncthreads();
#pragma unroll
                for (int it = 0; it < 4; it++) {
                    const int   kk = 8 * it + wid;                 // warp-uniform
                    const float cr = __shfl_sync(0xffffffffu, cO, kk);
                    const float sr = __shfl_sync(0xffffffffu, sO, kk);
                    const int   pq = __shfl_sync(0xffffffffu, pqPack, kk);
                    const int   pr = pq & 255, qr = pq >> 8;
                    const int   rp = pr * 65, rq = qr * 65;

                    if (sr != 0.f || sO != 0.f) {
                        const float a00 = Asm[rp + p], a01 = Asm[rp + q];
                        const float a10 = Asm[rq + p], a11 = Asm[rq + q];
                        const float b00 = cr * a00 - sr * a10;
                        const float b01 = cr * a01 - sr * a11;
                        const float b10 = sr * a00 + cr * a10;
                        const float b11 = sr * a01 + cr * a11;
                        Asm[rp + p] = cO * b00 - sO * b01;
                        Asm[rp + q] = sO * b00 + cO * b01;
                        Asm[rq + p] = cO * b10 - sO * b11;
                        Asm[rq + q] = sO * b10 + cO * b11;
                    }
                    if (sr != 0.f) {
                        float2* vp = (float2*)(Vsm + pr * 64) + lane;
                        float2* vq = (float2*)(Vsm + qr * 64) + lane;
                        const float2 xp = *vp, xq = *vq;
                        float2 np, nq;
                        np.x = cr * xp.x - sr * xq.x;
                        np.y = cr * xp.y - sr * xq.y;
                        nq.x = sr * xp.x + cr * xq.x;
                        nq.y = sr * xp.y + cr * xq.y;
                        *vp = np; *vq = nq;
                    }
                }
                __syncthreads();
            }
        }

        if (sweep >= 4) {   // convergence never fires earlier; skip the cost
            float m = 0.f;
            for (int idx = tid; idx < 4096; idx += 256) {
                const int i = idx >> 6, j = idx & 63;
                if (i != j) m = fmaxf(m, fabsf(Asm[i * 65 + j]));
            }
#pragma unroll
            for (int off = 16; off; off >>= 1)
                m = fmaxf(m, __shfl_down_sync(0xffffffffu, m, off));
            if (lane == 0) red[wid] = m;
            __syncthreads();
            if (tid == 0) {
                float mm = red[0];
#pragma unroll
                for (int w = 1; w < 8; w++) mm = fmaxf(mm, red[w]);
                red[8] = mm;
            }
            __syncthreads();
            if (red[8] < tol) break;
        }
    }

    // ---- B = diag(log lambda) * Q  -> Asm ----
    if (tid < 64) {
        const float d = Asm[tid * 65 + tid];
        logl[tid] = logf(fmaxf(d, 1e-6f));
    }
    __syncthreads();
    for (int idx = tid; idx < 4096; idx += 256) {
        const int k = idx >> 6, i = idx & 63;
        Asm[k * 65 + i] = logl[k] * Vsm[idx];
    }
    __syncthreads();

    // ---- log_cov = B^T Q via 4x4 block GEMM, triu written straight to vec ----
    {
        float acc[16];
#pragma unroll
        for (int r = 0; r < 16; r++) acc[r] = 0.f;
        for (int k = 0; k < 64; k++) {
            float bb[4];
#pragma unroll
            for (int r = 0; r < 4; r++) bb[r] = Asm[k * 65 + 4 * ti + r];
            const float4 qv = *((const float4*)(Vsm + k * 64) + tj);
#pragma unroll
            for (int r = 0; r < 4; r++) {
                acc[r * 4 + 0] += bb[r] * qv.x;
                acc[r * 4 + 1] += bb[r] * qv.y;
                acc[r * 4 + 2] += bb[r] * qv.z;
                acc[r * 4 + 3] += bb[r] * qv.w;
            }
        }
        __syncthreads();   // Asm/Vsm reads done before vec (Wbuf) is written
#pragma unroll
        for (int r = 0; r < 4; r++) {
#pragma unroll
            for (int u = 0; u < 4; u++) {
                const int i = 4 * ti + r, j = 4 * tj + u;
                if (i <= j && j < 62)
                    vec[i * (125 - i) / 2 + (j - i)] = acc[r * 4 + u];
            }
        }
    }
    __syncthreads();

    // ---- MLP: feat = relu(vec @ proj^T + b), 8 outputs per warp ----
    {
#pragma unroll
        for (int hh = 0; hh < 8; hh++) {
            const int h = (wid << 3) + hh;
            const float* pw = proj_w + h * 1953;
            float acc = 0.f;
            for (int i = lane; i < 1953; i += 32) acc += vec[i] * pw[i];
#pragma unroll
            for (int off = 16; off; off >>= 1)
                acc += __shfl_down_sync(0xffffffffu, acc, off);
            if (lane == 0) feat[h] = fmaxf(acc + proj_b[h], 0.f);
        }
    }
    __syncthreads();

    // ---- head: 3 logits ----
    if (tid < 3) {
        float acc = head_b[tid];
        const float* hw = head_w + tid * 64;
#pragma unroll
        for (int h = 0; h < 64; h++) acc += feat[h] * hw[h];
        out[b * 3 + tid] = acc;
    }
}

// ---------------------------------------------------------------------------
extern "C" void kernel_launch(void* const* d_in, const int* in_sizes, int n_in,
                              void* d_out, int out_size)
{
    const float* x      = (const float*)d_in[0];
    const float* conv_w = (const float*)d_in[1];
    // d_in[2] = conv_b: cancels exactly under mean-centering; unused.
    const float* proj_w = (const float*)d_in[3];
    const float* proj_b = (const float*)d_in[4];
    const float* head_w = (const float*)d_in[5];
    const float* head_b = (const float*)d_in[6];

    int B = in_sizes[0] / (CCH * TT);
    if (B > NB) B = NB;

    cov_kernel<<<B * NCHUNK, 256>>>(x);
    eig_kernel<<<B, 256>>>(conv_w, proj_w, proj_b, head_w, head_b, (float*)d_out);
}

// round 7
// speedup vs baseline: 1.1566x; 1.1566x over previous
#include <cuda_runtime.h>
#include <math.h>

#define CCH 62
#define TT  2000
#define NB  256
#define TIL 128
#define NTILE ((TT + TIL - 1) / TIL)   // 16

// scratch: per-batch padded 64x64 covariance of x (mean-corrected)
__device__ float g_cx[NB * 64 * 64];

// ---------------------------------------------------------------------------
// Kernel 1: per-batch covariance of raw x (centered), padded to 64x64.
// Triangular 4x4-block mapping (136 active threads), float4 smem loads.
// (R3 version — measured ~256us; chunked split-K variant regressed.)
// ---------------------------------------------------------------------------
__global__ __launch_bounds__(256, 2) void cov_kernel(const float* __restrict__ x)
{
    __shared__ __align__(16) float xs[64 * 132];
    __shared__ float ssum[64];

    const int b   = blockIdx.x;
    const int tid = threadIdx.x;

    int bi = 0, bj = 0;
    const bool act = (tid < 136);
    if (act) {
        int z = tid;
        while (z >= 16 - bi) { z -= 16 - bi; bi++; }
        bj = bi + z;
    }

    float acc[16];
#pragma unroll
    for (int r = 0; r < 16; r++) acc[r] = 0.f;
    float mysum = 0.f;

    const float* xb = x + (size_t)b * CCH * TT;

    for (int tile = 0; tile < NTILE; tile++) {
        const int t0 = tile * TIL;
        for (int idx = tid; idx < 64 * TIL; idx += 256) {
            const int c  = idx >> 7;
            const int tl = idx & 127;
            const int t  = t0 + tl;
            float v = 0.f;
            if (c < CCH && t < TT) v = xb[c * TT + t];
            xs[c * 132 + tl] = v;
        }
        __syncthreads();

        if (tid < CCH) {
            const float4* rp = (const float4*)(xs + tid * 132);
#pragma unroll 8
            for (int tl = 0; tl < 32; tl++) {
                const float4 v = rp[tl];
                mysum += (v.x + v.y) + (v.z + v.w);
            }
        }

        if (act) {
            const float4* r0 = (const float4*)(xs + (4 * bi + 0) * 132);
            const float4* r1 = (const float4*)(xs + (4 * bi + 1) * 132);
            const float4* r2 = (const float4*)(xs + (4 * bi + 2) * 132);
            const float4* r3 = (const float4*)(xs + (4 * bi + 3) * 132);
            const float4* c0 = (const float4*)(xs + (4 * bj + 0) * 132);
            const float4* c1 = (const float4*)(xs + (4 * bj + 1) * 132);
            const float4* c2 = (const float4*)(xs + (4 * bj + 2) * 132);
            const float4* c3 = (const float4*)(xs + (4 * bj + 3) * 132);

#pragma unroll 2
            for (int tl = 0; tl < 32; tl++) {
                const float4 a0 = r0[tl], a1 = r1[tl], a2 = r2[tl], a3 = r3[tl];
                const float4 b0 = c0[tl], b1 = c1[tl], b2 = c2[tl], b3 = c3[tl];
#define DOT4(A, B) ((A.x * B.x + A.y * B.y) + (A.z * B.z + A.w * B.w))
                acc[0]  += DOT4(a0, b0); acc[1]  += DOT4(a0, b1);
                acc[2]  += DOT4(a0, b2); acc[3]  += DOT4(a0, b3);
                acc[4]  += DOT4(a1, b0); acc[5]  += DOT4(a1, b1);
                acc[6]  += DOT4(a1, b2); acc[7]  += DOT4(a1, b3);
                acc[8]  += DOT4(a2, b0); acc[9]  += DOT4(a2, b1);
                acc[10] += DOT4(a2, b2); acc[11] += DOT4(a2, b3);
                acc[12] += DOT4(a3, b0); acc[13] += DOT4(a3, b1);
                acc[14] += DOT4(a3, b2); acc[15] += DOT4(a3, b3);
#undef DOT4
            }
        }
        __syncthreads();
    }

    if (tid < 64) ssum[tid] = (tid < CCH) ? mysum : 0.f;
    __syncthreads();

    if (act) {
        float* outp = g_cx + b * 4096;
#pragma unroll
        for (int r = 0; r < 4; r++) {
#pragma unroll
            for (int u = 0; u < 4; u++) {
                const int i = 4 * bi + r;
                const int j = 4 * bj + u;
                const float v =
                    (acc[r * 4 + u] - ssum[i] * ssum[j] * (1.f / 2000.f)) * (1.f / 1999.f);
                outp[i * 64 + j] = v;
                outp[j * 64 + i] = v;
            }
        }
    }
}

// ---------------------------------------------------------------------------
// Kernel 2: A = W Cx W^T + eps I -> fused two-sided Jacobi (pipelined,
// branch-free inner loop) -> log-map GEMM -> triu -> MLP. One CTA per batch.
// ---------------------------------------------------------------------------
__global__ __launch_bounds__(256, 2) void eig_kernel(
    const float* __restrict__ conv_w,
    const float* __restrict__ proj_w, const float* __restrict__ proj_b,
    const float* __restrict__ head_w, const float* __restrict__ head_b,
    float* __restrict__ out)
{
    __shared__ float Asm[64 * 65];                  // stride 65
    __shared__ __align__(16) float Vsm[64 * 64];    // stride 64
    __shared__ float Wbuf[62 * 62];                 // W in prologue; scratch after

    float* vec  = Wbuf;              // [1953]  (Wbuf dead when live)
    float* logl = Wbuf + 2048;       // [64]
    float* feat = Wbuf + 2112;       // [64]
    float* red  = Wbuf + 2176;       // [9]

    const int b    = blockIdx.x;
    const int tid  = threadIdx.x;
    const int wid  = tid >> 5;
    const int lane = tid & 31;
    const int ti   = tid >> 4;
    const int tj   = tid & 15;

    // ---- load Cx (into Asm) and W ----
    for (int idx = tid; idx < 4096; idx += 256)
        Asm[(idx >> 6) * 65 + (idx & 63)] = g_cx[b * 4096 + idx];
    for (int idx = tid; idx < 62 * 62; idx += 256) Wbuf[idx] = conv_w[idx];
    __syncthreads();

    // ---- M = W * Cx  -> Vsm ----
    {
        float acc[16];
#pragma unroll
        for (int r = 0; r < 16; r++) acc[r] = 0.f;
        for (int k = 0; k < 62; k++) {
            float wv[4], cv[4];
#pragma unroll
            for (int r = 0; r < 4; r++) {
                const int i = 4 * ti + r;
                wv[r] = (i < 62) ? Wbuf[i * 62 + k] : 0.f;
            }
#pragma unroll
            for (int u = 0; u < 4; u++) cv[u] = Asm[k * 65 + 4 * tj + u];
#pragma unroll
            for (int r = 0; r < 4; r++)
#pragma unroll
                for (int u = 0; u < 4; u++) acc[r * 4 + u] += wv[r] * cv[u];
        }
#pragma unroll
        for (int r = 0; r < 4; r++)
#pragma unroll
            for (int u = 0; u < 4; u++)
                Vsm[(4 * ti + r) * 64 + 4 * tj + u] = acc[r * 4 + u];
    }
    __syncthreads();

    // ---- A = M * W^T  -> Asm ----
    {
        float acc[16];
#pragma unroll
        for (int r = 0; r < 16; r++) acc[r] = 0.f;
        for (int k = 0; k < 62; k++) {
            float mv[4], wv[4];
#pragma unroll
            for (int r = 0; r < 4; r++) mv[r] = Vsm[(4 * ti + r) * 64 + k];
#pragma unroll
            for (int u = 0; u < 4; u++) {
                const int j = 4 * tj + u;
                wv[u] = (j < 62) ? Wbuf[j * 62 + k] : 0.f;
            }
#pragma unroll
            for (int r = 0; r < 4; r++)
#pragma unroll
                for (int u = 0; u < 4; u++) acc[r * 4 + u] += mv[r] * wv[u];
        }
#pragma unroll
        for (int r = 0; r < 4; r++)
#pragma unroll
            for (int u = 0; u < 4; u++)
                Asm[(4 * ti + r) * 65 + 4 * tj + u] = acc[r * 4 + u];
    }
    __syncthreads();

    // ---- symmetrize + SPD eps + pad diag ----
    {
        float v[16];
#pragma unroll
        for (int r = 0; r < 4; r++)
#pragma unroll
            for (int u = 0; u < 4; u++) {
                const int i = 4 * ti + r, j = 4 * tj + u;
                v[r * 4 + u] = 0.5f * (Asm[i * 65 + j] + Asm[j * 65 + i]);
            }
        __syncthreads();
#pragma unroll
        for (int r = 0; r < 4; r++)
#pragma unroll
            for (int u = 0; u < 4; u++) {
                const int i = 4 * ti + r, j = 4 * tj + u;
                float val = v[r * 4 + u];
                if (i == j) val = (i < 62) ? val + 1e-3f : 1.0f;
                Asm[i * 65 + j] = val;
            }
    }
    // V = I
    for (int idx = tid; idx < 4096; idx += 256)
        Vsm[idx] = ((idx >> 6) == (idx & 63)) ? 1.f : 0.f;
    __syncthreads();

    // ---- fused two-sided parallel Jacobi, pipelined branch-free inner loop ----
    // Relative skip: pair with apq^2 <= 1e-12*app*aqq gets (c,s)=(1,0);
    // identity rotations are applied unconditionally (bit-identical writes),
    // keeping the inner loop branch-free so all loads batch (MLP ~8).
    const float tol = 1e-5f;
    for (int sweep = 0; sweep < 9; sweep++) {
        bool any_sweep_rot = false;
        for (int r = 0; r < 63; r++) {
            int p, q;
            if (lane == 0) { p = 63; q = r; }
            else {
                p = r + lane;      if (p >= 63) p -= 63;
                q = r + 63 - lane; if (q >= 63) q -= 63;
            }
            const float app = Asm[p * 65 + p];
            const float aqq = Asm[q * 65 + q];
            const float apq = Asm[p * 65 + q];
            float cO = 1.f, sO = 0.f;
            if (apq * apq > 1e-12f * app * aqq) {
                const float tau = (aqq - app) / (2.f * apq);
                const float t2  = ((tau >= 0.f) ? 1.f : -1.f) /
                                  (fabsf(tau) + sqrtf(1.f + tau * tau));
                cO = rsqrtf(1.f + t2 * t2);
                sO = t2 * cO;
            }
            const int pqPack = p | (q << 8);
            const unsigned rotmask = __ballot_sync(0xffffffffu, sO != 0.f);
            if (rotmask == 0u) continue;
            any_sweep_rot = true;

            __syncthreads();   // rot-reads done before writes

            // gather all 4 its' params first
            float cr[4], sr[4];
            int   rp[4], rq[4];
#pragma unroll
            for (int it = 0; it < 4; it++) {
                const int kk = 8 * it + wid;                       // warp-uniform
                cr[it] = __shfl_sync(0xffffffffu, cO, kk);
                sr[it] = __shfl_sync(0xffffffffu, sO, kk);
                const int pq = __shfl_sync(0xffffffffu, pqPack, kk);
                rp[it] = (pq & 255) * 65;
                rq[it] = (pq >> 8) * 65;
            }
            // batched loads: A 2x2 blocks (rows pr,qr x cols p,q) + V row pairs
            float a00[4], a01[4], a10[4], a11[4];
            float2 xp[4], xq[4];
#pragma unroll
            for (int it = 0; it < 4; it++) {
                a00[it] = Asm[rp[it] + p]; a01[it] = Asm[rp[it] + q];
                a10[it] = Asm[rq[it] + p]; a11[it] = Asm[rq[it] + q];
            }
#pragma unroll
            for (int it = 0; it < 4; it++) {
                xp[it] = *((float2*)(Vsm + (rp[it] / 65) * 64) + lane);
                xq[it] = *((float2*)(Vsm + (rq[it] / 65) * 64) + lane);
            }
            // compute + store (disjoint elements across its -> no hazards)
#pragma unroll
            for (int it = 0; it < 4; it++) {
                const float b00 = cr[it] * a00[it] - sr[it] * a10[it];
                const float b01 = cr[it] * a01[it] - sr[it] * a11[it];
                const float b10 = sr[it] * a00[it] + cr[it] * a10[it];
                const float b11 = sr[it] * a01[it] + cr[it] * a11[it];
                Asm[rp[it] + p] = cO * b00 - sO * b01;
                Asm[rp[it] + q] = sO * b00 + cO * b01;
                Asm[rq[it] + p] = cO * b10 - sO * b11;
                Asm[rq[it] + q] = sO * b10 + cO * b11;
            }
#pragma unroll
            for (int it = 0; it < 4; it++) {
                float2 np, nq;
                np.x = cr[it] * xp[it].x - sr[it] * xq[it].x;
                np.y = cr[it] * xp[it].y - sr[it] * xq[it].y;
                nq.x = sr[it] * xp[it].x + cr[it] * xq[it].x;
                nq.y = sr[it] * xp[it].y + cr[it] * xq[it].y;
                *((float2*)(Vsm + (rp[it] / 65) * 64) + lane) = np;
                *((float2*)(Vsm + (rq[it] / 65) * 64) + lane) = nq;
            }
            __syncthreads();   // writes visible before next round's rot-reads
        }

        if (!any_sweep_rot) break;   // fully converged sweep: done

        if (sweep >= 4) {
            float m = 0.f;
            for (int idx = tid; idx < 4096; idx += 256) {
                const int i = idx >> 6, j = idx & 63;
                if (i != j) m = fmaxf(m, fabsf(Asm[i * 65 + j]));
            }
#pragma unroll
            for (int off = 16; off; off >>= 1)
                m = fmaxf(m, __shfl_down_sync(0xffffffffu, m, off));
            if (lane == 0) red[wid] = m;
            __syncthreads();
            if (tid == 0) {
                float mm = red[0];
#pragma unroll
                for (int w = 1; w < 8; w++) mm = fmaxf(mm, red[w]);
                red[8] = mm;
            }
            __syncthreads();
            if (red[8] < tol) break;
        }
    }

    // ---- B = diag(log lambda) * Q  -> Asm ----
    if (tid < 64) {
        const float d = Asm[tid * 65 + tid];
        logl[tid] = logf(fmaxf(d, 1e-6f));
    }
    __syncthreads();
    for (int idx = tid; idx < 4096; idx += 256) {
        const int k = idx >> 6, i = idx & 63;
        Asm[k * 65 + i] = logl[k] * Vsm[idx];
    }
    __syncthreads();

    // ---- log_cov = B^T Q via 4x4 block GEMM, triu straight to vec ----
    {
        float acc[16];
#pragma unroll
        for (int r = 0; r < 16; r++) acc[r] = 0.f;
        for (int k = 0; k < 64; k++) {
            float bb[4];
#pragma unroll
            for (int r = 0; r < 4; r++) bb[r] = Asm[k * 65 + 4 * ti + r];
            const float4 qv = *((const float4*)(Vsm + k * 64) + tj);
#pragma unroll
            for (int r = 0; r < 4; r++) {
                acc[r * 4 + 0] += bb[r] * qv.x;
                acc[r * 4 + 1] += bb[r] * qv.y;
                acc[r * 4 + 2] += bb[r] * qv.z;
                acc[r * 4 + 3] += bb[r] * qv.w;
            }
        }
        __syncthreads();   // Asm/Vsm reads done before vec (Wbuf) written
#pragma unroll
        for (int r = 0; r < 4; r++) {
#pragma unroll
            for (int u = 0; u < 4; u++) {
                const int i = 4 * ti + r, j = 4 * tj + u;
                if (i <= j && j < 62)
                    vec[i * (125 - i) / 2 + (j - i)] = acc[r * 4 + u];
            }
        }
    }
    __syncthreads();

    // ---- MLP: feat = relu(vec @ proj^T + b), 8 outputs per warp ----
    {
#pragma unroll
        for (int hh = 0; hh < 8; hh++) {
            const int h = (wid << 3) + hh;
            const float* pw = proj_w + h * 1953;
            float acc = 0.f;
            for (int i = lane; i < 1953; i += 32) acc += vec[i] * pw[i];
#pragma unroll
            for (int off = 16; off; off >>= 1)
                acc += __shfl_down_sync(0xffffffffu, acc, off);
            if (lane == 0) feat[h] = fmaxf(acc + proj_b[h], 0.f);
        }
    }
    __syncthreads();

    // ---- head: 3 logits ----
    if (tid < 3) {
        float acc = head_b[tid];
        const float* hw = head_w + tid * 64;
#pragma unroll
        for (int h = 0; h < 64; h++) acc += feat[h] * hw[h];
        out[b * 3 + tid] = acc;
    }
}

// ---------------------------------------------------------------------------
extern "C" void kernel_launch(void* const* d_in, const int* in_sizes, int n_in,
                              void* d_out, int out_size)
{
    const float* x      = (const float*)d_in[0];
    const float* conv_w = (const float*)d_in[1];
    // d_in[2] = conv_b: cancels exactly under mean-centering; unused.
    const float* proj_w = (const float*)d_in[3];
    const float* proj_b = (const float*)d_in[4];
    const float* head_w = (const float*)d_in[5];
    const float* head_b = (const float*)d_in[6];

    int B = in_sizes[0] / (CCH * TT);
    if (B > NB) B = NB;

    cov_kernel<<<B, 256>>>(x);
    eig_kernel<<<B, 256>>>(conv_w, proj_w, proj_b, head_w, head_b, (float*)d_out);
}

// round 8
// speedup vs baseline: 1.3234x; 1.1442x over previous
#include <cuda_runtime.h>
#include <math.h>

#define CCH 62
#define TT  2000
#define NB  256
#define TIL 128
#define NTILE ((TT + TIL - 1) / TIL)   // 16

// scratch: per-batch padded 64x64 covariance of x (mean-corrected)
__device__ float g_cx[NB * 64 * 64];

// ---------------------------------------------------------------------------
// Kernel 1: per-batch covariance of raw x (centered), padded to 64x64.
// R2-proven compute loop: triangular 4x4-block mapping (136 active threads),
// float2 smem reads at row stride 130 (conflict-free). Load phase upgraded
// to float2 global loads (TT=2000 even -> clean predication).
// ---------------------------------------------------------------------------
__global__ __launch_bounds__(256, 2) void cov_kernel(const float* __restrict__ x)
{
    __shared__ float xs[64 * 130];
    __shared__ float ssum[64];

    const int b   = blockIdx.x;
    const int tid = threadIdx.x;

    int bi = 0, bj = 0;
    const bool act = (tid < 136);
    if (act) {
        int z = tid;
        while (z >= 16 - bi) { z -= 16 - bi; bi++; }
        bj = bi + z;
    }

    float acc[16];
#pragma unroll
    for (int r = 0; r < 16; r++) acc[r] = 0.f;
    float mysum = 0.f;

    const float* xb = x + (size_t)b * CCH * TT;

    for (int tile = 0; tile < NTILE; tile++) {
        const int t0 = tile * TIL;
        // load tile [64 x 128] as float2 (rows >= 62 / t >= TT zero-filled)
#pragma unroll
        for (int k = 0; k < 16; k++) {
            const int f = tid + (k << 8);    // float2 id 0..4095
            const int c = f >> 6;            // 64 float2 per row
            const int u = f & 63;
            const int t = t0 + u * 2;
            float2 v = make_float2(0.f, 0.f);
            if (c < CCH && t < TT) v = *(const float2*)(xb + c * TT + t);
            *(float2*)(xs + c * 130 + u * 2) = v;
        }
        __syncthreads();

        if (tid < CCH) {
            const float2* rp = (const float2*)(xs + tid * 130);
#pragma unroll 8
            for (int tl = 0; tl < 64; tl++) {
                const float2 v = rp[tl];
                mysum += v.x + v.y;
            }
        }

        if (act) {
            const float2* r0 = (const float2*)(xs + (4 * bi + 0) * 130);
            const float2* r1 = (const float2*)(xs + (4 * bi + 1) * 130);
            const float2* r2 = (const float2*)(xs + (4 * bi + 2) * 130);
            const float2* r3 = (const float2*)(xs + (4 * bi + 3) * 130);
            const float2* c0 = (const float2*)(xs + (4 * bj + 0) * 130);
            const float2* c1 = (const float2*)(xs + (4 * bj + 1) * 130);
            const float2* c2 = (const float2*)(xs + (4 * bj + 2) * 130);
            const float2* c3 = (const float2*)(xs + (4 * bj + 3) * 130);

#pragma unroll 4
            for (int tl = 0; tl < 64; tl++) {
                const float2 a0 = r0[tl], a1 = r1[tl], a2 = r2[tl], a3 = r3[tl];
                const float2 b0 = c0[tl], b1 = c1[tl], b2 = c2[tl], b3 = c3[tl];
                acc[0]  += a0.x * b0.x + a0.y * b0.y;
                acc[1]  += a0.x * b1.x + a0.y * b1.y;
                acc[2]  += a0.x * b2.x + a0.y * b2.y;
                acc[3]  += a0.x * b3.x + a0.y * b3.y;
                acc[4]  += a1.x * b0.x + a1.y * b0.y;
                acc[5]  += a1.x * b1.x + a1.y * b1.y;
                acc[6]  += a1.x * b2.x + a1.y * b2.y;
                acc[7]  += a1.x * b3.x + a1.y * b3.y;
                acc[8]  += a2.x * b0.x + a2.y * b0.y;
                acc[9]  += a2.x * b1.x + a2.y * b1.y;
                acc[10] += a2.x * b2.x + a2.y * b2.y;
                acc[11] += a2.x * b3.x + a2.y * b3.y;
                acc[12] += a3.x * b0.x + a3.y * b0.y;
                acc[13] += a3.x * b1.x + a3.y * b1.y;
                acc[14] += a3.x * b2.x + a3.y * b2.y;
                acc[15] += a3.x * b3.x + a3.y * b3.y;
            }
        }
        __syncthreads();
    }

    if (tid < 64) ssum[tid] = (tid < CCH) ? mysum : 0.f;
    __syncthreads();

    if (act) {
        float* outp = g_cx + b * 4096;
#pragma unroll
        for (int r = 0; r < 4; r++) {
#pragma unroll
            for (int u = 0; u < 4; u++) {
                const int i = 4 * bi + r;
                const int j = 4 * bj + u;
                const float v =
                    (acc[r * 4 + u] - ssum[i] * ssum[j] * (1.f / 2000.f)) * (1.f / 1999.f);
                outp[i * 64 + j] = v;
                outp[j * 64 + i] = v;
            }
        }
    }
}

// ---------------------------------------------------------------------------
// Kernel 2: A = W Cx W^T + eps I -> fused two-sided Jacobi (pipelined,
// branch-free inner loop, relative skip 1e-10) -> log-map GEMM -> triu ->
// MLP. One CTA per batch.
// ---------------------------------------------------------------------------
__global__ __launch_bounds__(256, 2) void eig_kernel(
    const float* __restrict__ conv_w,
    const float* __restrict__ proj_w, const float* __restrict__ proj_b,
    const float* __restrict__ head_w, const float* __restrict__ head_b,
    float* __restrict__ out)
{
    __shared__ float Asm[64 * 65];                  // stride 65
    __shared__ __align__(16) float Vsm[64 * 64];    // stride 64
    __shared__ float Wbuf[62 * 62];                 // W in prologue; scratch after

    float* vec  = Wbuf;              // [1953]  (Wbuf dead when live)
    float* logl = Wbuf + 2048;       // [64]
    float* feat = Wbuf + 2112;       // [64]

    const int b    = blockIdx.x;
    const int tid  = threadIdx.x;
    const int wid  = tid >> 5;
    const int lane = tid & 31;
    const int ti   = tid >> 4;
    const int tj   = tid & 15;

    // ---- load Cx (into Asm) and W ----
    for (int idx = tid; idx < 4096; idx += 256)
        Asm[(idx >> 6) * 65 + (idx & 63)] = g_cx[b * 4096 + idx];
    for (int idx = tid; idx < 62 * 62; idx += 256) Wbuf[idx] = conv_w[idx];
    __syncthreads();

    // ---- M = W * Cx  -> Vsm ----
    {
        float acc[16];
#pragma unroll
        for (int r = 0; r < 16; r++) acc[r] = 0.f;
        for (int k = 0; k < 62; k++) {
            float wv[4], cv[4];
#pragma unroll
            for (int r = 0; r < 4; r++) {
                const int i = 4 * ti + r;
                wv[r] = (i < 62) ? Wbuf[i * 62 + k] : 0.f;
            }
#pragma unroll
            for (int u = 0; u < 4; u++) cv[u] = Asm[k * 65 + 4 * tj + u];
#pragma unroll
            for (int r = 0; r < 4; r++)
#pragma unroll
                for (int u = 0; u < 4; u++) acc[r * 4 + u] += wv[r] * cv[u];
        }
#pragma unroll
        for (int r = 0; r < 4; r++)
#pragma unroll
            for (int u = 0; u < 4; u++)
                Vsm[(4 * ti + r) * 64 + 4 * tj + u] = acc[r * 4 + u];
    }
    __syncthreads();

    // ---- A = M * W^T  -> Asm ----
    {
        float acc[16];
#pragma unroll
        for (int r = 0; r < 16; r++) acc[r] = 0.f;
        for (int k = 0; k < 62; k++) {
            float mv[4], wv[4];
#pragma unroll
            for (int r = 0; r < 4; r++) mv[r] = Vsm[(4 * ti + r) * 64 + k];
#pragma unroll
            for (int u = 0; u < 4; u++) {
                const int j = 4 * tj + u;
                wv[u] = (j < 62) ? Wbuf[j * 62 + k] : 0.f;
            }
#pragma unroll
            for (int r = 0; r < 4; r++)
#pragma unroll
                for (int u = 0; u < 4; u++) acc[r * 4 + u] += mv[r] * wv[u];
        }
#pragma unroll
        for (int r = 0; r < 4; r++)
#pragma unroll
            for (int u = 0; u < 4; u++)
                Asm[(4 * ti + r) * 65 + 4 * tj + u] = acc[r * 4 + u];
    }
    __syncthreads();

    // ---- symmetrize + SPD eps + pad diag ----
    {
        float v[16];
#pragma unroll
        for (int r = 0; r < 4; r++)
#pragma unroll
            for (int u = 0; u < 4; u++) {
                const int i = 4 * ti + r, j = 4 * tj + u;
                v[r * 4 + u] = 0.5f * (Asm[i * 65 + j] + Asm[j * 65 + i]);
            }
        __syncthreads();
#pragma unroll
        for (int r = 0; r < 4; r++)
#pragma unroll
            for (int u = 0; u < 4; u++) {
                const int i = 4 * ti + r, j = 4 * tj + u;
                float val = v[r * 4 + u];
                if (i == j) val = (i < 62) ? val + 1e-3f : 1.0f;
                Asm[i * 65 + j] = val;
            }
    }
    // V = I
    for (int idx = tid; idx < 4096; idx += 256)
        Vsm[idx] = ((idx >> 6) == (idx & 63)) ? 1.f : 0.f;
    __syncthreads();

    // ---- fused two-sided parallel Jacobi, branch-free inner loop ----
    // Relative skip at 1e-10: a skipped pair's log_cov error is bounded by
    // 1e-5 per entry independent of eigenvalue scale, since
    // sqrt(u)*log(u)/(u-1) <= 1 for u = lambda_p/lambda_q.
    for (int sweep = 0; sweep < 9; sweep++) {
        bool any_sweep_rot = false;
        for (int r = 0; r < 63; r++) {
            int p, q;
            if (lane == 0) { p = 63; q = r; }
            else {
                p = r + lane;      if (p >= 63) p -= 63;
                q = r + 63 - lane; if (q >= 63) q -= 63;
            }
            const float app = Asm[p * 65 + p];
            const float aqq = Asm[q * 65 + q];
            const float apq = Asm[p * 65 + q];
            float cO = 1.f, sO = 0.f;
            if (apq * apq > 1e-10f * app * aqq) {
                const float tau = (aqq - app) / (2.f * apq);
                const float t2  = ((tau >= 0.f) ? 1.f : -1.f) /
                                  (fabsf(tau) + sqrtf(1.f + tau * tau));
                cO = rsqrtf(1.f + t2 * t2);
                sO = t2 * cO;
            }
            const int pqPack = p | (q << 8);
            const unsigned rotmask = __ballot_sync(0xffffffffu, sO != 0.f);
            if (rotmask == 0u) continue;
            any_sweep_rot = true;

            __syncthreads();   // rot-reads done before writes

            float cr[4], sr[4];
            int   rp[4], rq[4];
#pragma unroll
            for (int it = 0; it < 4; it++) {
                const int kk = 8 * it + wid;                       // warp-uniform
                cr[it] = __shfl_sync(0xffffffffu, cO, kk);
                sr[it] = __shfl_sync(0xffffffffu, sO, kk);
                const int pq = __shfl_sync(0xffffffffu, pqPack, kk);
                rp[it] = (pq & 255) * 65;
                rq[it] = (pq >> 8) * 65;
            }
            float a00[4], a01[4], a10[4], a11[4];
            float2 xp[4], xq[4];
#pragma unroll
            for (int it = 0; it < 4; it++) {
                a00[it] = Asm[rp[it] + p]; a01[it] = Asm[rp[it] + q];
                a10[it] = Asm[rq[it] + p]; a11[it] = Asm[rq[it] + q];
            }
#pragma unroll
            for (int it = 0; it < 4; it++) {
                xp[it] = *((float2*)(Vsm + (rp[it] / 65) * 64) + lane);
                xq[it] = *((float2*)(Vsm + (rq[it] / 65) * 64) + lane);
            }
#pragma unroll
            for (int it = 0; it < 4; it++) {
                const float b00 = cr[it] * a00[it] - sr[it] * a10[it];
                const float b01 = cr[it] * a01[it] - sr[it] * a11[it];
                const float b10 = sr[it] * a00[it] + cr[it] * a10[it];
                const float b11 = sr[it] * a01[it] + cr[it] * a11[it];
                Asm[rp[it] + p] = cO * b00 - sO * b01;
                Asm[rp[it] + q] = sO * b00 + cO * b01;
                Asm[rq[it] + p] = cO * b10 - sO * b11;
                Asm[rq[it] + q] = sO * b10 + cO * b11;
            }
#pragma unroll
            for (int it = 0; it < 4; it++) {
                float2 np, nq;
                np.x = cr[it] * xp[it].x - sr[it] * xq[it].x;
                np.y = cr[it] * xp[it].y - sr[it] * xq[it].y;
                nq.x = sr[it] * xp[it].x + cr[it] * xq[it].x;
                nq.y = sr[it] * xp[it].y + cr[it] * xq[it].y;
                *((float2*)(Vsm + (rp[it] / 65) * 64) + lane) = np;
                *((float2*)(Vsm + (rq[it] / 65) * 64) + lane) = nq;
            }
            __syncthreads();   // writes visible before next round's rot-reads
        }

        if (!any_sweep_rot) break;   // all pairs below threshold: converged
    }

    // ---- B = diag(log lambda) * Q  -> Asm ----
    if (tid < 64) {
        const float d = Asm[tid * 65 + tid];
        logl[tid] = logf(fmaxf(d, 1e-6f));
    }
    __syncthreads();
    for (int idx = tid; idx < 4096; idx += 256) {
        const int k = idx >> 6, i = idx & 63;
        Asm[k * 65 + i] = logl[k] * Vsm[idx];
    }
    __syncthreads();

    // ---- log_cov = B^T Q via 4x4 block GEMM, triu straight to vec ----
    {
        float acc[16];
#pragma unroll
        for (int r = 0; r < 16; r++) acc[r] = 0.f;
        for (int k = 0; k < 64; k++) {
            float bb[4];
#pragma unroll
            for (int r = 0; r < 4; r++) bb[r] = Asm[k * 65 + 4 * ti + r];
            const float4 qv = *((const float4*)(Vsm + k * 64) + tj);
#pragma unroll
            for (int r = 0; r < 4; r++) {
                acc[r * 4 + 0] += bb[r] * qv.x;
                acc[r * 4 + 1] += bb[r] * qv.y;
                acc[r * 4 + 2] += bb[r] * qv.z;
                acc[r * 4 + 3] += bb[r] * qv.w;
            }
        }
        __syncthreads();   // Asm/Vsm reads done before vec (Wbuf) written
#pragma unroll
        for (int r = 0; r < 4; r++) {
#pragma unroll
            for (int u = 0; u < 4; u++) {
                const int i = 4 * ti + r, j = 4 * tj + u;
                if (i <= j && j < 62)
                    vec[i * (125 - i) / 2 + (j - i)] = acc[r * 4 + u];
            }
        }
    }
    __syncthreads();

    // ---- MLP: feat = relu(vec @ proj^T + b), 8 outputs per warp ----
    {
#pragma unroll
        for (int hh = 0; hh < 8; hh++) {
            const int h = (wid << 3) + hh;
            const float* pw = proj_w + h * 1953;
            float acc = 0.f;
            for (int i = lane; i < 1953; i += 32) acc += vec[i] * pw[i];
#pragma unroll
            for (int off = 16; off; off >>= 1)
                acc += __shfl_down_sync(0xffffffffu, acc, off);
            if (lane == 0) feat[h] = fmaxf(acc + proj_b[h], 0.f);
        }
    }
    __syncthreads();

    // ---- head: 3 logits ----
    if (tid < 3) {
        float acc = head_b[tid];
        const float* hw = head_w + tid * 64;
#pragma unroll
        for (int h = 0; h < 64; h++) acc += feat[h] * hw[h];
        out[b * 3 + tid] = acc;
    }
}

// ---------------------------------------------------------------------------
extern "C" void kernel_launch(void* const* d_in, const int* in_sizes, int n_in,
                              void* d_out, int out_size)
{
    const float* x      = (const float*)d_in[0];
    const float* conv_w = (const float*)d_in[1];
    // d_in[2] = conv_b: cancels exactly under mean-centering; unused.
    const float* proj_w = (const float*)d_in[3];
    const float* proj_b = (const float*)d_in[4];
    const float* head_w = (const float*)d_in[5];
    const float* head_b = (const float*)d_in[6];

    int B = in_sizes[0] / (CCH * TT);
    if (B > NB) B = NB;

    cov_kernel<<<B, 256>>>(x);
    eig_kernel<<<B, 256>>>(conv_w, proj_w, proj_b, head_w, head_b, (float*)d_out);
}